// round 16
// baseline (speedup 1.0000x reference)
#include <cuda_runtime.h>
#include <cuda_bf16.h>
#include <math.h>
#include <stdint.h>

#define S_SPK 1024
#define U_UTT 64
#define E_DIM 256
#define SU (S_SPK * U_UTT)
#define LOG2E 1.4426950408889634f
#define LN2 0.6931471805599453f
#define BAND 0.015f         // row-verdict margin in log2-logit units (~9 sigma of bf16 noise)
#define NTILE 512           // row tiles (128 rows each)

// ---------------- scratch ----------------
__device__ __nv_bfloat16 g_Ab[(size_t)SU * E_DIM];   // embeds bf16
__device__ __nv_bfloat16 g_Bb[S_SPK * E_DIM];        // normalized centroids bf16
__device__ float g_Bn[S_SPK * E_DIM];                // fp32 normalized centroids (recheck)
__device__ float g_diag[SU];
__device__ float g_psum[2 * SU];                     // per-half softmax partial sums
__device__ float g_pbv[2 * SU];                      // per-half max off-diag logit
__device__ float g_acc[2];
__device__ unsigned int g_nund;
__device__ unsigned int g_undlist[SU];               // each row appended at most once
__device__ unsigned int g_cnt[NTILE];                // per-row-tile arrival counters
__device__ unsigned int g_done;

// ---------------- helpers ----------------
__device__ __forceinline__ uint32_t smem_u32(const void* p) {
    uint32_t a;
    asm("{ .reg .u64 t; cvta.to.shared.u64 t, %1; cvt.u32.u64 %0, t; }" : "=r"(a) : "l"(p));
    return a;
}
__device__ __forceinline__ void cp16(uint32_t dst, const void* src) {
    asm volatile("cp.async.cg.shared.global [%0], [%1], 16;" :: "r"(dst), "l"(src));
}
#define CP_COMMIT() asm volatile("cp.async.commit_group;" ::: "memory")
#define CP_WAIT2()  asm volatile("cp.async.wait_group 2;" ::: "memory")

__device__ __forceinline__ void ldsm4(uint32_t* r, uint32_t addr) {
    asm volatile("ldmatrix.sync.aligned.m8n8.x4.shared.b16 {%0,%1,%2,%3}, [%4];"
                 : "=r"(r[0]), "=r"(r[1]), "=r"(r[2]), "=r"(r[3]) : "r"(addr));
}
__device__ __forceinline__ void mma16816(float* c, const uint32_t* a, uint32_t b0, uint32_t b1) {
    asm volatile("mma.sync.aligned.m16n8k16.row.col.f32.bf16.bf16.f32 "
                 "{%0,%1,%2,%3}, {%4,%5,%6,%7}, {%8,%9}, {%0,%1,%2,%3};"
                 : "+f"(c[0]), "+f"(c[1]), "+f"(c[2]), "+f"(c[3])
                 : "r"(a[0]), "r"(a[1]), "r"(a[2]), "r"(a[3]), "r"(b0), "r"(b1));
}

// ---------------------------------------------------------------------------
// Kernel 1: speaker sums -> normalized dirs (fp32 + bf16), diag cosines,
//           embed bf16 conversion. Block 0 also resets all run state.
// ---------------------------------------------------------------------------
__global__ void centroid_kernel(const float* __restrict__ emb) {
    int j = blockIdx.x;
    int t = threadIdx.x;  // E column
    if (j == 0) {
        if (t == 0) { g_acc[0] = 0.f; g_acc[1] = 0.f; g_nund = 0; g_done = 0; }
        for (int w = t; w < NTILE; w += 256) g_cnt[w] = 0;
    }
    const float* base = emb + (size_t)j * U_UTT * E_DIM;

    float sum = 0.f;
#pragma unroll
    for (int u = 0; u < U_UTT; u++) {
        float x = base[u * E_DIM + t];
        sum += x;
        g_Ab[((size_t)j * U_UTT + u) * E_DIM + t] = __float2bfloat16_rn(x);
    }

    __shared__ float sum_sh[E_DIM];
    __shared__ float red[8];
    __shared__ float ssq_sh;
    sum_sh[t] = sum;

    float v = sum * sum;
#pragma unroll
    for (int o = 16; o > 0; o >>= 1) v += __shfl_xor_sync(0xffffffffu, v, o);
    if ((t & 31) == 0) red[t >> 5] = v;
    __syncthreads();
    if (t == 0) {
        float tot = 0.f;
#pragma unroll
        for (int i = 0; i < 8; i++) tot += red[i];
        ssq_sh = tot;
    }
    __syncthreads();
    float ssq = ssq_sh;
    float bn = sum_sh[t] * rsqrtf(ssq);
    g_Bn[(size_t)j * E_DIM + t] = bn;
    g_Bb[(size_t)j * E_DIM + t] = __float2bfloat16_rn(bn);

    int warp = t >> 5, lane = t & 31;
    for (int u = warp; u < U_UTT; u += 8) {
        const float* row = base + u * E_DIM;
        float d = 0.f, n2 = 0.f;
#pragma unroll
        for (int i = 0; i < 8; i++) {
            float x = row[lane + 32 * i];
            d  += x * sum_sh[lane + 32 * i];
            n2 += x * x;
        }
#pragma unroll
        for (int o = 16; o > 0; o >>= 1) {
            d  += __shfl_xor_sync(0xffffffffu, d,  o);
            n2 += __shfl_xor_sync(0xffffffffu, n2, o);
        }
        if (lane == 0) {
            float denom = ssq - 2.f * d + n2;
            g_diag[j * U_UTT + u] = (d - n2) * rsqrtf(denom);
        }
    }
}

// ---------------------------------------------------------------------------
// Main kernel: single-term bf16 GEMM, block = 128 rows x 512 cols (grid 1024,
// half = blockIdx&1). Per-half softmax partials; the LAST block of each row
// tile (arrival counter) performs the combine: loss + verdict + worklist.
// SMEM: A 64K | B ring 3x16K | red 1K.
// ---------------------------------------------------------------------------
#define AB_OFF 0
#define BB_OFF 65536
#define RED_OFF (BB_OFF + 3 * 16384)
#define SMEM_TOTAL (RED_OFF + 1024)

__global__ __launch_bounds__(256, 2)
void ge2e_main_kernel(const float* __restrict__ wp, const float* __restrict__ bp)
{
    extern __shared__ char smem[];
    const uint32_t sb = smem_u32(smem);
    const int tid = threadIdx.x;
    const int lane = tid & 31, wid = tid >> 5;
    const int wr = wid >> 1;          // row-group 0..3
    const int cg = wid & 1;           // col-group 0..1
    const int rowTile = blockIdx.x >> 1;
    const int rowBase = rowTile * 128;
    const int half = blockIdx.x & 1;
    const int colOff = half * 512;

    const float wS = wp[0], bS = bp[0];
    const float w2 = wS * LOG2E, b2 = (bS - 5.f) * LOG2E;
    const __nv_bfloat16* Bsrc = g_Bb + (size_t)colOff * E_DIM;

    // ---- prologue: A + B chunks 0..2 ----
#pragma unroll
    for (int k = 0; k < 16; k++) {
        int i = tid + k * 256;
        int row = i >> 5, c = i & 31;
        cp16(sb + AB_OFF + row * 512 + ((c ^ (row & 7)) << 4),
             g_Ab + (size_t)(rowBase + row) * E_DIM + c * 8);
    }
#pragma unroll
    for (int g0 = 0; g0 < 3; g0++) {
#pragma unroll
        for (int it = 0; it < 4; it++) {
            int idx = tid + it * 256;
            int row = idx >> 3, c = idx & 7;
            cp16(sb + BB_OFF + g0 * 16384 + row * 128 + ((c ^ (row & 7)) << 4),
                 Bsrc + (size_t)row * E_DIM + g0 * 64 + c * 8);
        }
        CP_COMMIT();
    }

    // ---- per-thread row state ----
    float sum[4] = {0.f, 0.f, 0.f, 0.f};
    float bv[4], t2d[4];
    int spk[4], rloc[4];
#pragma unroll
    for (int mt = 0; mt < 2; mt++)
#pragma unroll
        for (int rb = 0; rb < 2; rb++) {
            int si = mt * 2 + rb;
            int r = wr * 32 + mt * 16 + rb * 8 + (lane >> 2);
            rloc[si] = r;
            int rg = rowBase + r;
            spk[si] = rg >> 6;
            t2d[si] = fmaf(w2, g_diag[rg], b2);
            bv[si] = -1e30f;
        }

    const int sA = lane & 7;
    const int hA = lane >> 4;
    const uint32_t aRow0 = sb + AB_OFF + (uint32_t)(wr * 32 + (lane & 15)) * 512;
    const int bRow = cg * 64 + (lane & 7) + ((lane >> 4) & 1) * 8;
    const int hB = (lane >> 3) & 1;

    float c_[2][8][4];

    for (int g = 0; g < 16; g++) {               // chunk: tile = g>>2, k64 = g&3
        if ((g & 3) == 0) {
#pragma unroll
            for (int mt = 0; mt < 2; mt++)
#pragma unroll
                for (int nt = 0; nt < 8; nt++)
#pragma unroll
                    for (int q = 0; q < 4; q++) c_[mt][nt][q] = 0.f;
        }

        CP_WAIT2();
        __syncthreads();
        const uint32_t Bb = sb + BB_OFF + (uint32_t)(g % 3) * 16384;

#pragma unroll
        for (int kc = 0; kc < 4; kc++) {
            const int kg = (g & 3) * 4 + kc;
            uint32_t a[2][4];
#pragma unroll
            for (int mt = 0; mt < 2; mt++)
                ldsm4(a[mt], aRow0 + (uint32_t)(mt * 16) * 512 +
                             (uint32_t)(((2 * kg + hA) ^ sA) << 4));
            uint32_t b[4][4];
#pragma unroll
            for (int np = 0; np < 4; np++)
                ldsm4(b[np], Bb + (uint32_t)(bRow + np * 16) * 128 +
                             (uint32_t)(((2 * kc + hB) ^ sA) << 4));
#pragma unroll
            for (int mt = 0; mt < 2; mt++)
#pragma unroll
                for (int nt = 0; nt < 8; nt++)
                    mma16816(c_[mt][nt], a[mt], b[nt >> 1][(nt & 1) * 2],
                             b[nt >> 1][(nt & 1) * 2 + 1]);
        }
        __syncthreads();                          // slot free before overwrite

        if (g + 3 < 16) {
            int gn = g + 3;
            int tileN = gn >> 2, k64 = gn & 3, slot = gn % 3;
#pragma unroll
            for (int it = 0; it < 4; it++) {
                int idx = tid + it * 256;
                int row = idx >> 3, c = idx & 7;
                cp16(sb + BB_OFF + slot * 16384 + row * 128 + ((c ^ (row & 7)) << 4),
                     Bsrc + (size_t)(tileN * 128 + row) * E_DIM + k64 * 64 + c * 8);
            }
        }
        CP_COMMIT();

        if ((g & 3) == 3) {
            const int ct = g >> 2;
#pragma unroll
            for (int mt = 0; mt < 2; mt++)
#pragma unroll
                for (int nt = 0; nt < 8; nt++) {
                    int c0 = colOff + ct * 128 + cg * 64 + nt * 8 + 2 * (lane & 3);
#pragma unroll
                    for (int rb = 0; rb < 2; rb++) {
                        int si = mt * 2 + rb;
#pragma unroll
                        for (int q = 0; q < 2; q++) {
                            int cc = c0 + q;
                            float raw = fmaf(w2, c_[mt][nt][rb * 2 + q], b2);
                            float ls;
                            if (cc == spk[si]) {
                                ls = t2d[si];          // exact diag, excluded from bv
                            } else {
                                ls = raw;
                                if (raw > bv[si]) bv[si] = raw;
                            }
                            float e;
                            asm("ex2.approx.ftz.f32 %0, %1;" : "=f"(e) : "f"(ls));
                            sum[si] += e;
                        }
                    }
                }
        }
    }

    // ---- quad reduce ----
#pragma unroll
    for (int si = 0; si < 4; si++) {
#pragma unroll
        for (int o = 1; o < 4; o <<= 1) {
            sum[si] += __shfl_xor_sync(0xffffffffu, sum[si], o);
            float obv = __shfl_xor_sync(0xffffffffu, bv[si], o);
            if (obv > bv[si]) bv[si] = obv;
        }
    }

    // ---- cross col-group combine, write per-half partials ----
    float* s_sum = (float*)(smem + RED_OFF);
    float* s_bv  = (float*)(smem + RED_OFF + 512);
    __syncthreads();
    if (cg == 1 && (lane & 3) == 0) {
#pragma unroll
        for (int si = 0; si < 4; si++) { s_sum[rloc[si]] = sum[si]; s_bv[rloc[si]] = bv[si]; }
    }
    __syncthreads();
    if (cg == 0 && (lane & 3) == 0) {
#pragma unroll
        for (int si = 0; si < 4; si++) {
            int rg = rowBase + rloc[si];
            g_psum[half * SU + rg] = sum[si] + s_sum[rloc[si]];
            g_pbv[half * SU + rg]  = fmaxf(bv[si], s_bv[rloc[si]]);
        }
    }

    // ---- last block of this row tile does the per-row combine ----
    __syncthreads();
    __threadfence();
    __shared__ unsigned prev_sh;
    if (tid == 0) prev_sh = atomicAdd(&g_cnt[rowTile], 1u);
    __syncthreads();
    if (prev_sh == 1u) {
        float lossLocal = 0.f, corrLocal = 0.f;
        if (tid < 128) {
            int r = rowBase + tid;
            float td = fmaf(w2, g_diag[r], b2);
            float tot = g_psum[r] + g_psum[SU + r];
            float bvv = fmaxf(g_pbv[r], g_pbv[SU + r]);
            lossLocal = __logf(tot) - td * LN2;
            if (bvv < td - BAND) {
                corrLocal = 1.f;                  // definitely correct
            } else if (bvv < td + BAND) {         // undecided -> worklist
                unsigned int idx = atomicAdd(&g_nund, 1u);
                g_undlist[idx] = (unsigned)r;
            }
        }
#pragma unroll
        for (int o = 16; o > 0; o >>= 1) {
            lossLocal += __shfl_xor_sync(0xffffffffu, lossLocal, o);
            corrLocal += __shfl_xor_sync(0xffffffffu, corrLocal, o);
        }
        float* redL = (float*)(smem + RED_OFF);   // reuse (post-barrier safe)
        float* redC = (float*)(smem + RED_OFF + 64);
        if ((tid & 31) == 0 && tid < 128) { redL[tid >> 5] = lossLocal; redC[tid >> 5] = corrLocal; }
        __syncthreads();
        if (tid == 0) {
            float L = 0.f, C = 0.f;
#pragma unroll
            for (int i = 0; i < 4; i++) { L += redL[i]; C += redC[i]; }
            atomicAdd(&g_acc[0], L);
            atomicAdd(&g_acc[1], C);
        }
    }
}

// ---------------------------------------------------------------------------
// Stage 2: exact fp32 verdict, ONE BLOCK PER UNDECIDED ROW (grid-stride over
// the compacted list) + fused finalize (last block writes outputs).
// ---------------------------------------------------------------------------
__global__ void recheck_kernel(const float* __restrict__ emb, float* __restrict__ out) {
    __shared__ float e_sh[E_DIM];
    __shared__ int beaten_sh;
    int tid = threadIdx.x;
    unsigned int n = g_nund;
    for (unsigned int i = blockIdx.x; i < n; i += gridDim.x) {
        int r = g_undlist[i];

        if (tid < 128) {
            e_sh[tid] = emb[(size_t)r * E_DIM + tid];
            e_sh[tid + 128] = emb[(size_t)r * E_DIM + tid + 128];
        }
        if (tid == 0) beaten_sh = 0;
        __syncthreads();

        int spk = r >> 6;
        float diag = g_diag[r];
        int beat = 0;
#pragma unroll
        for (int cc = 0; cc < 4; cc++) {
            int c = tid + cc * 256;
            const float4* bn = (const float4*)(g_Bn + (size_t)c * E_DIM);
            float d0 = 0.f, d1 = 0.f;
#pragma unroll
            for (int k = 0; k < 32; k++) {
                float4 v0 = bn[2 * k], v1 = bn[2 * k + 1];
                const float4 e0 = *(const float4*)(e_sh + 8 * k);
                const float4 e1 = *(const float4*)(e_sh + 8 * k + 4);
                d0 = fmaf(v0.x, e0.x, d0); d0 = fmaf(v0.y, e0.y, d0);
                d0 = fmaf(v0.z, e0.z, d0); d0 = fmaf(v0.w, e0.w, d0);
                d1 = fmaf(v1.x, e1.x, d1); d1 = fmaf(v1.y, e1.y, d1);
                d1 = fmaf(v1.z, e1.z, d1); d1 = fmaf(v1.w, e1.w, d1);
            }
            float d = d0 + d1;
            if (c != spk && (d > diag || (d == diag && c < spk))) beat = 1;
        }
        if (beat) atomicOr(&beaten_sh, 1);
        __syncthreads();
        if (tid == 0 && !beaten_sh) atomicAdd(&g_acc[1], 1.f);
        __syncthreads();
    }

    // ---- fused finalize: last block writes the outputs ----
    __threadfence();
    __syncthreads();
    if (tid == 0) {
        unsigned prev = atomicAdd(&g_done, 1u);
        if (prev == gridDim.x - 1) {
            out[0] = g_acc[0] * (1.f / (float)SU);
            out[1] = g_acc[1] * (1.f / (float)SU);
        }
    }
}

extern "C" void kernel_launch(void* const* d_in, const int* in_sizes, int n_in,
                              void* d_out, int out_size) {
    const float* emb = (const float*)d_in[0];
    const float* wp  = (const float*)d_in[1];
    const float* bp  = (const float*)d_in[2];
    float* out = (float*)d_out;

    cudaFuncSetAttribute(ge2e_main_kernel,
                         cudaFuncAttributeMaxDynamicSharedMemorySize, SMEM_TOTAL);

    centroid_kernel<<<S_SPK, 256>>>(emb);
    ge2e_main_kernel<<<(SU / 128) * 2, 256, SMEM_TOTAL>>>(wp, bp);
    recheck_kernel<<<1024, 256>>>(emb, out);
}

// round 17
// speedup vs baseline: 1.4016x; 1.4016x over previous
#include <cuda_runtime.h>
#include <cuda_bf16.h>
#include <math.h>
#include <stdint.h>

#define S_SPK 1024
#define U_UTT 64
#define E_DIM 256
#define SU (S_SPK * U_UTT)
#define LOG2E 1.4426950408889634f
#define LN2 0.6931471805599453f
#define BAND 0.015f         // row-verdict margin in log2-logit units (~9 sigma of bf16 noise)

// ---------------- scratch ----------------
__device__ __nv_bfloat16 g_Ab[(size_t)SU * E_DIM];   // embeds bf16
__device__ __nv_bfloat16 g_Bb[S_SPK * E_DIM];        // normalized centroids bf16
__device__ float g_Bn[S_SPK * E_DIM];                // fp32 normalized centroids (recheck)
__device__ float g_diag[SU];
__device__ float g_psum[2 * SU];                     // per-half softmax partial sums
__device__ float g_pbv[2 * SU];                      // per-half max off-diag logit
__device__ float g_acc[2];
__device__ unsigned int g_nund;
__device__ unsigned int g_undlist[SU];               // each row appended at most once

// ---------------- helpers ----------------
__device__ __forceinline__ uint32_t smem_u32(const void* p) {
    uint32_t a;
    asm("{ .reg .u64 t; cvta.to.shared.u64 t, %1; cvt.u32.u64 %0, t; }" : "=r"(a) : "l"(p));
    return a;
}
__device__ __forceinline__ void cp16(uint32_t dst, const void* src) {
    asm volatile("cp.async.cg.shared.global [%0], [%1], 16;" :: "r"(dst), "l"(src));
}
#define CP_COMMIT() asm volatile("cp.async.commit_group;" ::: "memory")
#define CP_WAIT2()  asm volatile("cp.async.wait_group 2;" ::: "memory")

__device__ __forceinline__ void ldsm4(uint32_t* r, uint32_t addr) {
    asm volatile("ldmatrix.sync.aligned.m8n8.x4.shared.b16 {%0,%1,%2,%3}, [%4];"
                 : "=r"(r[0]), "=r"(r[1]), "=r"(r[2]), "=r"(r[3]) : "r"(addr));
}
__device__ __forceinline__ void mma16816(float* c, const uint32_t* a, uint32_t b0, uint32_t b1) {
    asm volatile("mma.sync.aligned.m16n8k16.row.col.f32.bf16.bf16.f32 "
                 "{%0,%1,%2,%3}, {%4,%5,%6,%7}, {%8,%9}, {%0,%1,%2,%3};"
                 : "+f"(c[0]), "+f"(c[1]), "+f"(c[2]), "+f"(c[3])
                 : "r"(a[0]), "r"(a[1]), "r"(a[2]), "r"(a[3]), "r"(b0), "r"(b1));
}

// ---------------------------------------------------------------------------
__global__ void zero_kernel() {
    g_acc[0] = 0.f; g_acc[1] = 0.f; g_nund = 0;
}

// ---------------------------------------------------------------------------
// Kernel 1: speaker sums -> normalized dirs (fp32 + bf16), diag cosines,
//           embed bf16 conversion.
// ---------------------------------------------------------------------------
__global__ void centroid_kernel(const float* __restrict__ emb) {
    int j = blockIdx.x;
    int t = threadIdx.x;  // E column
    const float* base = emb + (size_t)j * U_UTT * E_DIM;

    float sum = 0.f;
#pragma unroll
    for (int u = 0; u < U_UTT; u++) {
        float x = base[u * E_DIM + t];
        sum += x;
        g_Ab[((size_t)j * U_UTT + u) * E_DIM + t] = __float2bfloat16_rn(x);
    }

    __shared__ float sum_sh[E_DIM];
    __shared__ float red[8];
    __shared__ float ssq_sh;
    sum_sh[t] = sum;

    float v = sum * sum;
#pragma unroll
    for (int o = 16; o > 0; o >>= 1) v += __shfl_xor_sync(0xffffffffu, v, o);
    if ((t & 31) == 0) red[t >> 5] = v;
    __syncthreads();
    if (t == 0) {
        float tot = 0.f;
#pragma unroll
        for (int i = 0; i < 8; i++) tot += red[i];
        ssq_sh = tot;
    }
    __syncthreads();
    float ssq = ssq_sh;
    float bn = sum_sh[t] * rsqrtf(ssq);
    g_Bn[(size_t)j * E_DIM + t] = bn;
    g_Bb[(size_t)j * E_DIM + t] = __float2bfloat16_rn(bn);

    int warp = t >> 5, lane = t & 31;
    for (int u = warp; u < U_UTT; u += 8) {
        const float* row = base + u * E_DIM;
        float d = 0.f, n2 = 0.f;
#pragma unroll
        for (int i = 0; i < 8; i++) {
            float x = row[lane + 32 * i];
            d  += x * sum_sh[lane + 32 * i];
            n2 += x * x;
        }
#pragma unroll
        for (int o = 16; o > 0; o >>= 1) {
            d  += __shfl_xor_sync(0xffffffffu, d,  o);
            n2 += __shfl_xor_sync(0xffffffffu, n2, o);
        }
        if (lane == 0) {
            float denom = ssq - 2.f * d + n2;
            g_diag[j * U_UTT + u] = (d - n2) * rsqrtf(denom);
        }
    }
}

// ---------------------------------------------------------------------------
// Main kernel: single-term bf16 GEMM. Grid 1024: block = 128 rows x 512 cols
// (half = blockIdx&1) -> per-block time halves, wave quantization 4->7 of
// smaller blocks. Softmax partials written per (half,row); loss/verdict in
// combine_kernel. SMEM: A 64K | B ring 3x16K | red 1K.
// ---------------------------------------------------------------------------
#define AB_OFF 0
#define BB_OFF 65536
#define RED_OFF (BB_OFF + 3 * 16384)
#define SMEM_TOTAL (RED_OFF + 1024)

__global__ __launch_bounds__(256, 2)
void ge2e_main_kernel(const float* __restrict__ wp, const float* __restrict__ bp)
{
    extern __shared__ char smem[];
    const uint32_t sb = smem_u32(smem);
    const int tid = threadIdx.x;
    const int lane = tid & 31, wid = tid >> 5;
    const int wr = wid >> 1;          // row-group 0..3
    const int cg = wid & 1;           // col-group 0..1
    const int rowBase = (blockIdx.x >> 1) * 128;
    const int half = blockIdx.x & 1;
    const int colOff = half * 512;    // this block's 512-column slice of B

    const float wS = wp[0], bS = bp[0];
    const float w2 = wS * LOG2E, b2 = (bS - 5.f) * LOG2E;
    const __nv_bfloat16* Bsrc = g_Bb + (size_t)colOff * E_DIM;

    // ---- prologue: A + B chunks 0..2 ----
#pragma unroll
    for (int k = 0; k < 16; k++) {
        int i = tid + k * 256;
        int row = i >> 5, c = i & 31;
        cp16(sb + AB_OFF + row * 512 + ((c ^ (row & 7)) << 4),
             g_Ab + (size_t)(rowBase + row) * E_DIM + c * 8);
    }
#pragma unroll
    for (int g0 = 0; g0 < 3; g0++) {
#pragma unroll
        for (int it = 0; it < 4; it++) {
            int idx = tid + it * 256;
            int row = idx >> 3, c = idx & 7;
            cp16(sb + BB_OFF + g0 * 16384 + row * 128 + ((c ^ (row & 7)) << 4),
                 Bsrc + (size_t)row * E_DIM + g0 * 64 + c * 8);
        }
        CP_COMMIT();
    }

    // ---- per-thread row state ----
    float sum[4] = {0.f, 0.f, 0.f, 0.f};
    float bv[4], t2d[4];
    int spk[4], rloc[4];
#pragma unroll
    for (int mt = 0; mt < 2; mt++)
#pragma unroll
        for (int rb = 0; rb < 2; rb++) {
            int si = mt * 2 + rb;
            int r = wr * 32 + mt * 16 + rb * 8 + (lane >> 2);
            rloc[si] = r;
            int rg = rowBase + r;
            spk[si] = rg >> 6;
            t2d[si] = fmaf(w2, g_diag[rg], b2);
            bv[si] = -1e30f;
        }

    const int sA = lane & 7;
    const int hA = lane >> 4;
    const uint32_t aRow0 = sb + AB_OFF + (uint32_t)(wr * 32 + (lane & 15)) * 512;
    const int bRow = cg * 64 + (lane & 7) + ((lane >> 4) & 1) * 8;
    const int hB = (lane >> 3) & 1;

    float c_[2][8][4];

    for (int g = 0; g < 16; g++) {               // chunk: tile = g>>2, k64 = g&3
        if ((g & 3) == 0) {
#pragma unroll
            for (int mt = 0; mt < 2; mt++)
#pragma unroll
                for (int nt = 0; nt < 8; nt++)
#pragma unroll
                    for (int q = 0; q < 4; q++) c_[mt][nt][q] = 0.f;
        }

        CP_WAIT2();
        __syncthreads();
        const uint32_t Bb = sb + BB_OFF + (uint32_t)(g % 3) * 16384;

#pragma unroll
        for (int kc = 0; kc < 4; kc++) {
            const int kg = (g & 3) * 4 + kc;
            uint32_t a[2][4];
#pragma unroll
            for (int mt = 0; mt < 2; mt++)
                ldsm4(a[mt], aRow0 + (uint32_t)(mt * 16) * 512 +
                             (uint32_t)(((2 * kg + hA) ^ sA) << 4));
            uint32_t b[4][4];
#pragma unroll
            for (int np = 0; np < 4; np++)
                ldsm4(b[np], Bb + (uint32_t)(bRow + np * 16) * 128 +
                             (uint32_t)(((2 * kc + hB) ^ sA) << 4));
#pragma unroll
            for (int mt = 0; mt < 2; mt++)
#pragma unroll
                for (int nt = 0; nt < 8; nt++)
                    mma16816(c_[mt][nt], a[mt], b[nt >> 1][(nt & 1) * 2],
                             b[nt >> 1][(nt & 1) * 2 + 1]);
        }
        __syncthreads();                          // slot free before overwrite

        if (g + 3 < 16) {
            int gn = g + 3;
            int tileN = gn >> 2, k64 = gn & 3, slot = gn % 3;
#pragma unroll
            for (int it = 0; it < 4; it++) {
                int idx = tid + it * 256;
                int row = idx >> 3, c = idx & 7;
                cp16(sb + BB_OFF + slot * 16384 + row * 128 + ((c ^ (row & 7)) << 4),
                     Bsrc + (size_t)(tileN * 128 + row) * E_DIM + k64 * 64 + c * 8);
            }
        }
        CP_COMMIT();

        if ((g & 3) == 3) {
            const int ct = g >> 2;
#pragma unroll
            for (int mt = 0; mt < 2; mt++)
#pragma unroll
                for (int nt = 0; nt < 8; nt++) {
                    int c0 = colOff + ct * 128 + cg * 64 + nt * 8 + 2 * (lane & 3);
#pragma unroll
                    for (int rb = 0; rb < 2; rb++) {
                        int si = mt * 2 + rb;
#pragma unroll
                        for (int q = 0; q < 2; q++) {
                            int cc = c0 + q;
                            float raw = fmaf(w2, c_[mt][nt][rb * 2 + q], b2);
                            float ls;
                            if (cc == spk[si]) {
                                ls = t2d[si];          // exact diag, excluded from bv
                            } else {
                                ls = raw;
                                if (raw > bv[si]) bv[si] = raw;
                            }
                            float e;
                            asm("ex2.approx.ftz.f32 %0, %1;" : "=f"(e) : "f"(ls));
                            sum[si] += e;
                        }
                    }
                }
        }
    }

    // ---- quad reduce ----
#pragma unroll
    for (int si = 0; si < 4; si++) {
#pragma unroll
        for (int o = 1; o < 4; o <<= 1) {
            sum[si] += __shfl_xor_sync(0xffffffffu, sum[si], o);
            float obv = __shfl_xor_sync(0xffffffffu, bv[si], o);
            if (obv > bv[si]) bv[si] = obv;
        }
    }

    // ---- cross col-group combine, write per-half partials (no atomics) ----
    float* s_sum = (float*)(smem + RED_OFF);
    float* s_bv  = (float*)(smem + RED_OFF + 512);
    __syncthreads();
    if (cg == 1 && (lane & 3) == 0) {
#pragma unroll
        for (int si = 0; si < 4; si++) { s_sum[rloc[si]] = sum[si]; s_bv[rloc[si]] = bv[si]; }
    }
    __syncthreads();
    if (cg == 0 && (lane & 3) == 0) {
#pragma unroll
        for (int si = 0; si < 4; si++) {
            int rg = rowBase + rloc[si];
            g_psum[half * SU + rg] = sum[si] + s_sum[rloc[si]];
            g_pbv[half * SU + rg]  = fmaxf(bv[si], s_bv[rloc[si]]);
        }
    }
}

// ---------------------------------------------------------------------------
// Combine: merge the two column halves per row -> loss + verdict + worklist.
// ---------------------------------------------------------------------------
__global__ void combine_kernel(const float* __restrict__ wp, const float* __restrict__ bp) {
    __shared__ float redL[8], redC[8];
    int r = blockIdx.x * 256 + threadIdx.x;
    const float wS = wp[0], bS = bp[0];
    const float w2 = wS * LOG2E, b2 = (bS - 5.f) * LOG2E;

    float t2d = fmaf(w2, g_diag[r], b2);
    float tot = g_psum[r] + g_psum[SU + r];
    float bv  = fmaxf(g_pbv[r], g_pbv[SU + r]);
    float lossLocal = __logf(tot) - t2d * LN2;
    float corrLocal = 0.f;
    if (bv < t2d - BAND) {
        corrLocal = 1.f;                          // definitely correct
    } else if (bv < t2d + BAND) {                 // undecided -> worklist
        unsigned int idx = atomicAdd(&g_nund, 1u);
        g_undlist[idx] = (unsigned)r;
    }

#pragma unroll
    for (int o = 16; o > 0; o >>= 1) {
        lossLocal += __shfl_xor_sync(0xffffffffu, lossLocal, o);
        corrLocal += __shfl_xor_sync(0xffffffffu, corrLocal, o);
    }
    int t = threadIdx.x;
    if ((t & 31) == 0) { redL[t >> 5] = lossLocal; redC[t >> 5] = corrLocal; }
    __syncthreads();
    if (t == 0) {
        float L = 0.f, C = 0.f;
#pragma unroll
        for (int i = 0; i < 8; i++) { L += redL[i]; C += redC[i]; }
        atomicAdd(&g_acc[0], L);
        atomicAdd(&g_acc[1], C);
    }
}

// ---------------------------------------------------------------------------
// Stage 2: exact fp32 verdict, ONE BLOCK PER UNDECIDED ROW (grid-stride over
// the compacted list). 256 threads, 4 cols/thread, 2 partial accumulators.
// ---------------------------------------------------------------------------
__global__ void recheck_kernel(const float* __restrict__ emb) {
    __shared__ float e_sh[E_DIM];
    __shared__ int beaten_sh;
    int tid = threadIdx.x;
    unsigned int n = g_nund;
    for (unsigned int i = blockIdx.x; i < n; i += gridDim.x) {
        int r = g_undlist[i];

        if (tid < 128) {
            e_sh[tid] = emb[(size_t)r * E_DIM + tid];
            e_sh[tid + 128] = emb[(size_t)r * E_DIM + tid + 128];
        }
        if (tid == 0) beaten_sh = 0;
        __syncthreads();

        int spk = r >> 6;
        float diag = g_diag[r];
        int beat = 0;
#pragma unroll
        for (int cc = 0; cc < 4; cc++) {
            int c = tid + cc * 256;
            const float4* bn = (const float4*)(g_Bn + (size_t)c * E_DIM);
            float d0 = 0.f, d1 = 0.f;
#pragma unroll
            for (int k = 0; k < 32; k++) {
                float4 v0 = bn[2 * k], v1 = bn[2 * k + 1];
                const float4 e0 = *(const float4*)(e_sh + 8 * k);
                const float4 e1 = *(const float4*)(e_sh + 8 * k + 4);
                d0 = fmaf(v0.x, e0.x, d0); d0 = fmaf(v0.y, e0.y, d0);
                d0 = fmaf(v0.z, e0.z, d0); d0 = fmaf(v0.w, e0.w, d0);
                d1 = fmaf(v1.x, e1.x, d1); d1 = fmaf(v1.y, e1.y, d1);
                d1 = fmaf(v1.z, e1.z, d1); d1 = fmaf(v1.w, e1.w, d1);
            }
            float d = d0 + d1;
            if (c != spk && (d > diag || (d == diag && c < spk))) beat = 1;
        }
        if (beat) atomicOr(&beaten_sh, 1);
        __syncthreads();
        if (tid == 0 && !beaten_sh) atomicAdd(&g_acc[1], 1.f);
        __syncthreads();
    }
}

// ---------------------------------------------------------------------------
__global__ void finalize_kernel(float* __restrict__ out) {
    out[0] = g_acc[0] * (1.f / (float)SU);
    out[1] = g_acc[1] * (1.f / (float)SU);
}

extern "C" void kernel_launch(void* const* d_in, const int* in_sizes, int n_in,
                              void* d_out, int out_size) {
    const float* emb = (const float*)d_in[0];
    const float* wp  = (const float*)d_in[1];
    const float* bp  = (const float*)d_in[2];
    float* out = (float*)d_out;

    cudaFuncSetAttribute(ge2e_main_kernel,
                         cudaFuncAttributeMaxDynamicSharedMemorySize, SMEM_TOTAL);

    zero_kernel<<<1, 1>>>();
    centroid_kernel<<<S_SPK, 256>>>(emb);
    ge2e_main_kernel<<<(SU / 128) * 2, 256, SMEM_TOTAL>>>(wp, bp);
    combine_kernel<<<SU / 256, 256>>>(wp, bp);
    recheck_kernel<<<1024, 256>>>(emb);
    finalize_kernel<<<1, 1>>>(out);
}